// round 3
// baseline (speedup 1.0000x reference)
#include <cuda_runtime.h>

#define B 256
#define S 512
#define T 128
#define STARTT 125
#define STOPT 126

// 64MB part-history scratch: hist[b][s][t]
__device__ float g_hist[(size_t)B * S * T];
// transposed transitions: transT[j][i] = trans[i][j]
__device__ float g_transT[T * T];

// ---------------------------------------------------------------------------
// Kernel 0: transpose transitions into g_transT
// ---------------------------------------------------------------------------
__global__ void k_transpose(const float* __restrict__ trans) {
    int j = blockIdx.x;   // 0..127
    int i = threadIdx.x;  // 0..127
    g_transT[j * T + i] = trans[i * T + j];
}

// ---------------------------------------------------------------------------
// Kernel 1: forward Viterbi max-plus recurrence. One block per batch.
// Thread j holds trans[:, j] in 128 registers. part broadcast via smem.
// Stores full part history (traceback recomputes argmax exactly from it).
// ---------------------------------------------------------------------------
__global__ __launch_bounds__(128, 2) void k_forward(
    const float* __restrict__ feats, const float* __restrict__ trans) {
    const int b = blockIdx.x;
    const int j = threadIdx.x;

    // trans column j into registers (coalesced per i across threads)
    float c[T];
#pragma unroll
    for (int i = 0; i < T; i++) c[i] = trans[i * T + j];

    __shared__ __align__(16) float part[2][T];

    const float* fb = feats + (size_t)b * S * T;
    float* hb = g_hist + (size_t)b * S * T;

    // s = 0: part0 = emit[0] + trans[START][:]
    float e0 = fb[j];
    float p0 = e0 + c[STARTT];
    part[0][j] = p0;
    hb[j] = p0;
    float e_next = fb[T + j];
    __syncthreads();

#pragma unroll 1
    for (int s = 1; s < S; s++) {
        float ecur = e_next;
        if (s + 1 < S) e_next = fb[(s + 1) * T + j];

        const float4* pp = reinterpret_cast<const float4*>(part[(s - 1) & 1]);
        float4 v0 = pp[0];
        float m0 = v0.x + c[0];
        float m1 = v0.y + c[1];
        float m2 = v0.z + c[2];
        float m3 = v0.w + c[3];
#pragma unroll
        for (int q = 1; q < 32; q++) {
            float4 u = pp[q];
            m0 = fmaxf(m0, u.x + c[4 * q + 0]);
            m1 = fmaxf(m1, u.y + c[4 * q + 1]);
            m2 = fmaxf(m2, u.z + c[4 * q + 2]);
            m3 = fmaxf(m3, u.w + c[4 * q + 3]);
        }
        float np = fmaxf(fmaxf(m0, m1), fmaxf(m2, m3)) + ecur;
        part[s & 1][j] = np;
        hb[s * T + j] = np;
        __syncthreads();
    }
}

// monotonic float -> u32 key (order preserving for finite floats)
__device__ __forceinline__ unsigned fkey(float f) {
    unsigned u = __float_as_uint(f);
    return u ^ ((unsigned)((int)u >> 31) | 0x80000000u);
}

// ---------------------------------------------------------------------------
// Kernel 2: lengths + final pointer + traceback (argmax recompute along path).
// One block per batch, 128 threads; warp 0 runs the serial trace.
// OUTPUT IS WRITTEN AS float32 (declared __output__ dtype; reference's int32
// decode is cast to float by the harness — int bit patterns read as denormals
// and produced the exact rel_err = 1.0 signature in R1/R2).
// ---------------------------------------------------------------------------
__global__ void k_traceback(const float* __restrict__ feats,
                            const void* __restrict__ mask,
                            float* __restrict__ out) {
    const int b = blockIdx.x;
    const int tid = threadIdx.x;

    __shared__ int s_len, s_ptr;
    __shared__ int swsum[4];
    __shared__ float sv[4];
    __shared__ int si[4];

    // ---- lengths: robust to mask dtype. lengths >= 256, so the first 32-bit
    // word of the mask buffer is a deterministic dtype signature. ----
    const unsigned* mw = (const unsigned*)mask;
    unsigned w0 = mw[0];
    int cnt = 0;
    int base = b * S + tid * 4;
    if (w0 == 0x01010101u) {  // 1-byte bool
        const unsigned char* m8 = (const unsigned char*)mask;
        cnt = (m8[base] != 0) + (m8[base + 1] != 0) + (m8[base + 2] != 0) +
              (m8[base + 3] != 0);
    } else if (w0 == 0x3F800000u) {  // float32
        const float* mf = (const float*)mask;
        cnt = (mf[base] != 0.f) + (mf[base + 1] != 0.f) +
              (mf[base + 2] != 0.f) + (mf[base + 3] != 0.f);
    } else if (w0 == 0x3F803F80u || w0 == 0x3C003C00u) {  // bf16 / f16 (1.0,1.0)
        const unsigned short* mh = (const unsigned short*)mask;
        cnt = (mh[base] != 0) + (mh[base + 1] != 0) + (mh[base + 2] != 0) +
              (mh[base + 3] != 0);
    } else {  // int32 0/1
        const int* mi = (const int*)mask;
        cnt = (mi[base] != 0) + (mi[base + 1] != 0) + (mi[base + 2] != 0) +
              (mi[base + 3] != 0);
    }
    cnt = __reduce_add_sync(0xffffffffu, cnt);
    if ((tid & 31) == 0) swsum[tid >> 5] = cnt;
    __syncthreads();
    if (tid == 0) s_len = swsum[0] + swsum[1] + swsum[2] + swsum[3];
    __syncthreads();
    const int last_pos = s_len - 1;

    // ---- final pointer: argmax_i(hist[last_pos][i] + trans[i][STOP]) ----
    float v = g_hist[((size_t)b * S + last_pos) * T + tid] +
              g_transT[STOPT * T + tid];
    int idx = tid;
#pragma unroll
    for (int off = 16; off; off >>= 1) {
        float ov = __shfl_down_sync(0xffffffffu, v, off);
        int oi = __shfl_down_sync(0xffffffffu, idx, off);
        if (ov > v || (ov == v && oi < idx)) { v = ov; idx = oi; }
    }
    if ((tid & 31) == 0) { sv[tid >> 5] = v; si[tid >> 5] = idx; }
    __syncthreads();
    if (tid == 0) {
        float bv = sv[0]; int bi = si[0];
#pragma unroll
        for (int w = 1; w < 4; w++)
            if (sv[w] > bv || (sv[w] == bv && si[w] < bi)) { bv = sv[w]; bi = si[w]; }
        s_ptr = bi;
    }
    __syncthreads();
    const int pointer = s_ptr;
    float* ob = out + b * S;

    // positions past the sequence: zeros (matches zeroed back_points rows)
    for (int s = last_pos + 1 + tid; s < S - 1; s += 128) ob[s] = 0.0f;
    if (tid == 0) {
        ob[S - 1] = (float)pointer;
        ob[last_pos] = (float)pointer;
    }
    if (tid >= 32) return;

    // ---- warp 0: serial traceback with exact argmax recompute ----
    const int l = tid;
    const float4* hist4 =
        reinterpret_cast<const float4*>(g_hist + (size_t)b * S * T);
    const float4* feats4 =
        reinterpret_cast<const float4*>(feats + (size_t)b * S * T);
    const float4* gT4 = reinterpret_cast<const float4*>(g_transT);

    int ptr = pointer;
    int s0 = last_pos - 1;
    if (s0 < 0) return;

    float4 h_cur = hist4[s0 * 32 + l];          // hist row s0
    float4 e_cur = feats4[(s0 + 1) * 32 + l];   // emit row s0+1

    for (int s = s0; s >= 0; --s) {
        // prefetch next step's rows (addresses independent of ptr)
        float4 h_nxt = h_cur, e_nxt = e_cur;
        if (s > 0) {
            h_nxt = hist4[(s - 1) * 32 + l];
            e_nxt = feats4[s * 32 + l];
        }

        float4 tc = __ldg(&gT4[ptr * 32 + l]);  // trans[:, ptr] chunk

        // scalar e = feats[b][s+1][ptr] extracted from prefetched row
        int comp = ptr & 3, src = ptr >> 2;
        float cand = (comp == 0) ? e_cur.x
                   : (comp == 1) ? e_cur.y
                   : (comp == 2) ? e_cur.z : e_cur.w;
        float e = __shfl_sync(0xffffffffu, cand, src);

        // exact replication of reference: (part + trans) + e, argmax first-idx
        float q0 = (h_cur.x + tc.x) + e;
        float q1 = (h_cur.y + tc.y) + e;
        float q2 = (h_cur.z + tc.z) + e;
        float q3 = (h_cur.w + tc.w) + e;
        unsigned k0 = fkey(q0), k1 = fkey(q1), k2 = fkey(q2), k3 = fkey(q3);
        unsigned ka = (k0 > k1) ? k0 : k1;
        unsigned kb = (k2 > k3) ? k2 : k3;
        unsigned lm = (ka > kb) ? ka : kb;
        unsigned g = __reduce_max_sync(0xffffffffu, lm);
        unsigned bm = (k0 == g ? 1u : 0u) | (k1 == g ? 2u : 0u) |
                      (k2 == g ? 4u : 0u) | (k3 == g ? 8u : 0u);
        unsigned bal = __ballot_sync(0xffffffffu, bm != 0u);
        int lane = __ffs((int)bal) - 1;
        int myidx = 4 * l + (__ffs((int)bm) - 1);
        ptr = __shfl_sync(0xffffffffu, myidx, lane);
        if (l == 0) ob[s] = (float)ptr;

        h_cur = h_nxt;
        e_cur = e_nxt;
    }
}

// ---------------------------------------------------------------------------
extern "C" void kernel_launch(void* const* d_in, const int* in_sizes, int n_in,
                              void* d_out, int out_size) {
    // Identify inputs by element count (robust to ordering):
    //   feats: 256*512*128 = 16777216, transitions: 128*128 = 16384,
    //   mask:  256*512    = 131072
    const float* feats = nullptr;
    const void* mask = nullptr;
    const float* trans = nullptr;
    for (int i = 0; i < n_in; i++) {
        int n = in_sizes[i];
        if (n == B * S * T) feats = (const float*)d_in[i];
        else if (n == T * T) trans = (const float*)d_in[i];
        else mask = d_in[i];
    }
    float* out = (float*)d_out;
    (void)out_size;

    k_transpose<<<T, T>>>(trans);
    k_forward<<<B, T>>>(feats, trans);
    k_traceback<<<B, T>>>(feats, mask, out);
}

// round 4
// speedup vs baseline: 1.0227x; 1.0227x over previous
#include <cuda_runtime.h>

#define B 256
#define S 512
#define T 128
#define STARTT 125
#define STOPT 126
#define TB_PITCH 132  // padded row pitch (floats) for smem transT

// 64MB part-history scratch: hist[b][s][t]
__device__ float g_hist[(size_t)B * S * T];
// transposed transitions: transT[j][i] = trans[i][j]
__device__ float g_transT[T * T];

// ---------------------------------------------------------------------------
// Kernel 0: transpose transitions into g_transT (tiny)
// ---------------------------------------------------------------------------
__global__ void k_transpose(const float* __restrict__ trans) {
    int j = blockIdx.x;
    int i = threadIdx.x;
    g_transT[j * T + i] = trans[i * T + j];
}

// ---------------------------------------------------------------------------
// Kernel 1: forward Viterbi max-plus recurrence. One block per batch.
// Thread j holds trans[:, j] packed as 64 f32x2 register pairs.
// Inner loop: ld.shared.v2.b64 + 2x add.rn.f32x2 + 4x max.f32 per 4 "from"
// states -> alu-pipe (FMNMX) bound at ~508 cyc/step/SMSP with 2 blocks/SM.
// ---------------------------------------------------------------------------
__global__ __launch_bounds__(128, 2) void k_forward(
    const float* __restrict__ feats, const float* __restrict__ trans) {
    const int b = blockIdx.x;
    const int j = threadIdx.x;

    // trans column j, packed into 64 x (f32,f32) register pairs
    unsigned long long c2[T / 2];
#pragma unroll
    for (int q = 0; q < T / 2; q++) {
        float lo = trans[(2 * q) * T + j];
        float hi = trans[(2 * q + 1) * T + j];
        asm("mov.b64 %0, {%1, %2};" : "=l"(c2[q]) : "f"(lo), "f"(hi));
    }
    // c[STARTT] = hi half of pair 62
    float cstart;
    {
        float dead;
        asm("mov.b64 {%0, %1}, %2;" : "=f"(dead), "=f"(cstart) : "l"(c2[STARTT / 2]));
        (void)dead;
    }

    __shared__ __align__(16) float part[2][T];

    const float* fb = feats + (size_t)b * S * T;
    float* hb = g_hist + (size_t)b * S * T;

    // s = 0: part0 = emit[0] + trans[START][:]
    float p0 = fb[j] + cstart;
    part[0][j] = p0;
    hb[j] = p0;
    float e_next = fb[T + j];
    __syncthreads();

    const unsigned sbase0 = (unsigned)__cvta_generic_to_shared(&part[0][0]);
    const unsigned sbase1 = (unsigned)__cvta_generic_to_shared(&part[1][0]);

#pragma unroll 1
    for (int s = 1; s < S; s++) {
        float ecur = e_next;
        if (s + 1 < S) e_next = fb[(s + 1) * T + j];

        const unsigned pbase = ((s - 1) & 1) ? sbase1 : sbase0;

        float m0, m1, m2, m3;
        // q = 0: initialize accumulators with the sums
        asm volatile(
            "{\n\t"
            ".reg .b64 p0, p1, s0, s1;\n\t"
            "ld.shared.v2.b64 {p0, p1}, [%4];\n\t"
            "add.rn.f32x2 s0, p0, %5;\n\t"
            "add.rn.f32x2 s1, p1, %6;\n\t"
            "mov.b64 {%0, %1}, s0;\n\t"
            "mov.b64 {%2, %3}, s1;\n\t"
            "}"
            : "=f"(m0), "=f"(m1), "=f"(m2), "=f"(m3)
            : "r"(pbase), "l"(c2[0]), "l"(c2[1]));
#pragma unroll
        for (int q = 1; q < 32; q++) {
            asm volatile(
                "{\n\t"
                ".reg .b64 p0, p1, s0, s1;\n\t"
                ".reg .f32 a0, a1, a2, a3;\n\t"
                "ld.shared.v2.b64 {p0, p1}, [%4];\n\t"
                "add.rn.f32x2 s0, p0, %5;\n\t"
                "add.rn.f32x2 s1, p1, %6;\n\t"
                "mov.b64 {a0, a1}, s0;\n\t"
                "mov.b64 {a2, a3}, s1;\n\t"
                "max.f32 %0, %0, a0;\n\t"
                "max.f32 %1, %1, a1;\n\t"
                "max.f32 %2, %2, a2;\n\t"
                "max.f32 %3, %3, a3;\n\t"
                "}"
                : "+f"(m0), "+f"(m1), "+f"(m2), "+f"(m3)
                : "r"(pbase + 16u * q), "l"(c2[2 * q]), "l"(c2[2 * q + 1]));
        }
        float np = fmaxf(fmaxf(m0, m1), fmaxf(m2, m3)) + ecur;
        part[s & 1][j] = np;
        hb[s * T + j] = np;
        __syncthreads();
    }
}

// monotonic float -> u32 key (order preserving for finite floats)
__device__ __forceinline__ unsigned fkey(float f) {
    unsigned u = __float_as_uint(f);
    return u ^ ((unsigned)((int)u >> 31) | 0x80000000u);
}

// ---------------------------------------------------------------------------
// Kernel 2: lengths + final pointer + traceback (argmax recompute along path).
// One block per batch, 128 threads; warp 0 runs the serial trace.
// transT in padded smem (pitch 132 -> conflict-free LDS.128 rows).
// ---------------------------------------------------------------------------
__global__ void k_traceback(const float* __restrict__ feats,
                            const void* __restrict__ mask,
                            float* __restrict__ out) {
    const int b = blockIdx.x;
    const int tid = threadIdx.x;

    extern __shared__ float sT[];  // [T][TB_PITCH]
    __shared__ int s_len, s_ptr;
    __shared__ int swsum[4];
    __shared__ float sv[4];
    __shared__ int si[4];

    // copy g_transT into padded smem (coalesced LDG.128, conflict-free STS)
    {
        const float4* g4 = reinterpret_cast<const float4*>(g_transT);
        for (int k4 = tid; k4 < T * T / 4; k4 += 128) {
            float4 v = g4[k4];
            int k = 4 * k4;
            int row = k >> 7, col = k & 127;
            float* dst = sT + row * TB_PITCH + col;
            dst[0] = v.x; dst[1] = v.y; dst[2] = v.z; dst[3] = v.w;
        }
    }

    // ---- lengths: robust to mask dtype (first word is a dtype signature,
    // since lengths >= 256 -> mask[0][0..3] all ones) ----
    const unsigned* mw = (const unsigned*)mask;
    unsigned w0 = mw[0];
    int cnt = 0;
    int base = b * S + tid * 4;
    if (w0 == 0x01010101u) {  // 1-byte bool
        const unsigned char* m8 = (const unsigned char*)mask;
        cnt = (m8[base] != 0) + (m8[base + 1] != 0) + (m8[base + 2] != 0) +
              (m8[base + 3] != 0);
    } else if (w0 == 0x3F800000u) {  // float32
        const float* mf = (const float*)mask;
        cnt = (mf[base] != 0.f) + (mf[base + 1] != 0.f) +
              (mf[base + 2] != 0.f) + (mf[base + 3] != 0.f);
    } else if (w0 == 0x3F803F80u || w0 == 0x3C003C00u) {  // bf16 / f16
        const unsigned short* mh = (const unsigned short*)mask;
        cnt = (mh[base] != 0) + (mh[base + 1] != 0) + (mh[base + 2] != 0) +
              (mh[base + 3] != 0);
    } else {  // int32 0/1
        const int* mi = (const int*)mask;
        cnt = (mi[base] != 0) + (mi[base + 1] != 0) + (mi[base + 2] != 0) +
              (mi[base + 3] != 0);
    }
    cnt = __reduce_add_sync(0xffffffffu, cnt);
    if ((tid & 31) == 0) swsum[tid >> 5] = cnt;
    __syncthreads();
    if (tid == 0) s_len = swsum[0] + swsum[1] + swsum[2] + swsum[3];
    __syncthreads();
    const int last_pos = s_len - 1;

    // ---- final pointer: argmax_i(hist[last_pos][i] + trans[i][STOP]) ----
    float v = g_hist[((size_t)b * S + last_pos) * T + tid] +
              sT[STOPT * TB_PITCH + tid];
    int idx = tid;
#pragma unroll
    for (int off = 16; off; off >>= 1) {
        float ov = __shfl_down_sync(0xffffffffu, v, off);
        int oi = __shfl_down_sync(0xffffffffu, idx, off);
        if (ov > v || (ov == v && oi < idx)) { v = ov; idx = oi; }
    }
    if ((tid & 31) == 0) { sv[tid >> 5] = v; si[tid >> 5] = idx; }
    __syncthreads();
    if (tid == 0) {
        float bv = sv[0]; int bi = si[0];
#pragma unroll
        for (int w = 1; w < 4; w++)
            if (sv[w] > bv || (sv[w] == bv && si[w] < bi)) { bv = sv[w]; bi = si[w]; }
        s_ptr = bi;
    }
    __syncthreads();
    const int pointer = s_ptr;
    float* ob = out + b * S;

    // positions past the sequence: zeros (matches zeroed back_points rows)
    for (int s = last_pos + 1 + tid; s < S - 1; s += 128) ob[s] = 0.0f;
    if (tid == 0) {
        ob[S - 1] = (float)pointer;
        ob[last_pos] = (float)pointer;
    }
    if (tid >= 32) return;

    // ---- warp 0: serial traceback with exact argmax recompute ----
    const int l = tid;
    const float4* hist4 =
        reinterpret_cast<const float4*>(g_hist + (size_t)b * S * T);
    const float4* feats4 =
        reinterpret_cast<const float4*>(feats + (size_t)b * S * T);

    int ptr = pointer;
    int s0 = last_pos - 1;
    if (s0 < 0) return;

    float4 h_cur = hist4[s0 * 32 + l];          // hist row s0
    float4 e_cur = feats4[(s0 + 1) * 32 + l];   // emit row s0+1

    for (int s = s0; s >= 0; --s) {
        // prefetch next step's rows (addresses independent of ptr)
        float4 h_nxt = h_cur, e_nxt = e_cur;
        if (s > 0) {
            h_nxt = hist4[(s - 1) * 32 + l];
            e_nxt = feats4[s * 32 + l];
        }

        // trans[:, ptr] chunk from padded smem (LDS.128, conflict-free)
        const float4* rowp =
            reinterpret_cast<const float4*>(sT + ptr * TB_PITCH);
        float4 tc = rowp[l];

        // scalar e = feats[b][s+1][ptr] extracted from prefetched row
        int comp = ptr & 3, src = ptr >> 2;
        float cand = (comp == 0) ? e_cur.x
                   : (comp == 1) ? e_cur.y
                   : (comp == 2) ? e_cur.z : e_cur.w;
        float e = __shfl_sync(0xffffffffu, cand, src);

        // exact replication of reference: (part + trans) + e, argmax first-idx
        float q0 = (h_cur.x + tc.x) + e;
        float q1 = (h_cur.y + tc.y) + e;
        float q2 = (h_cur.z + tc.z) + e;
        float q3 = (h_cur.w + tc.w) + e;
        unsigned k0 = fkey(q0), k1 = fkey(q1), k2 = fkey(q2), k3 = fkey(q3);
        unsigned ka = (k0 > k1) ? k0 : k1;
        unsigned kb = (k2 > k3) ? k2 : k3;
        unsigned lm = (ka > kb) ? ka : kb;
        unsigned g = __reduce_max_sync(0xffffffffu, lm);
        unsigned bm = (k0 == g ? 1u : 0u) | (k1 == g ? 2u : 0u) |
                      (k2 == g ? 4u : 0u) | (k3 == g ? 8u : 0u);
        unsigned idxc = bm ? (unsigned)(4 * l + (__ffs((int)bm) - 1))
                           : 0x40000000u;
        ptr = (int)__reduce_min_sync(0xffffffffu, idxc);
        if (l == 0) ob[s] = (float)ptr;

        h_cur = h_nxt;
        e_cur = e_nxt;
    }
}

// ---------------------------------------------------------------------------
extern "C" void kernel_launch(void* const* d_in, const int* in_sizes, int n_in,
                              void* d_out, int out_size) {
    // Identify inputs by element count:
    //   feats 16777216, transitions 16384, mask 131072
    const float* feats = nullptr;
    const void* mask = nullptr;
    const float* trans = nullptr;
    for (int i = 0; i < n_in; i++) {
        int n = in_sizes[i];
        if (n == B * S * T) feats = (const float*)d_in[i];
        else if (n == T * T) trans = (const float*)d_in[i];
        else mask = d_in[i];
    }
    float* out = (float*)d_out;
    (void)out_size;

    const int smem_tb = T * TB_PITCH * sizeof(float);  // 67584 B
    static int attr_done = 0;
    if (!attr_done) {
        cudaFuncSetAttribute(k_traceback,
                             cudaFuncAttributeMaxDynamicSharedMemorySize,
                             smem_tb);
        attr_done = 1;
    }

    k_transpose<<<T, T>>>(trans);
    k_forward<<<B, T>>>(feats, trans);
    k_traceback<<<B, T, smem_tb>>>(feats, mask, out);
}